// round 16
// baseline (speedup 1.0000x reference)
#include <cuda_runtime.h>
#include <cuda_fp16.h>
#include <cstdint>
#include <math.h>

// Problem constants
static constexpr int Bc  = 4;
static constexpr int Sc  = 1024;
static constexpr int Dc  = 1024;
static constexpr int Hc  = 16;
static constexpr int HDc = 64;
static constexpr int Lc  = 12;
static constexpr int BS  = Bc * Sc;       // 4096 rows

// ---------------------------------------------------------------------------
// Scratch (__device__ globals; no cudaMalloc allowed)
// ---------------------------------------------------------------------------
__device__ __half g_Xh[(size_t)BS * Dc];          // fp16 x operand
__device__ __half g_CtxH[(size_t)BS * Dc];        // fp16 ctx (attn output)
__device__ __half g_WH[(size_t)5 * Dc * Dc];      // [wqkv^T; wk^T; wv^T] fp16
__device__ __half g_WoH[(size_t)Dc * Dc];         // w_o^T fp16
__device__ __half g_QKVH[(size_t)BS * 3 * Dc];    // qkv fp16 (attn operands)
__device__ int    g_mcnt[32];                     // qkv m-block done (-> 24)
__device__ int    g_actx[32];                     // ctx m-block done (-> 16)
__device__ int    g_xcnt[32];                     // x-convert per m-block (-> 4)
__device__ int    g_misc[4];                      // [0]=wq(96) [1]=wkv(64) [2]=wo(32) [3]=xall(128)

// ---------------------------------------------------------------------------
// PTX helpers (base-PTX only: cp.async / ldmatrix / mma.sync)
// ---------------------------------------------------------------------------
__device__ __forceinline__ uint32_t smem_u32(const void* p) {
    uint32_t a;
    asm("{ .reg .u64 t; cvta.to.shared.u64 t, %1; cvt.u32.u64 %0, t; }"
        : "=r"(a) : "l"(p));
    return a;
}

__device__ __forceinline__ void cp16(uint32_t saddr, const void* gaddr) {
    asm volatile("cp.async.cg.shared.global [%0], [%1], 16;"
                 :: "r"(saddr), "l"(gaddr));
}
#define CP_COMMIT() asm volatile("cp.async.commit_group;" ::: "memory")
#define CP_WAIT(n)  asm volatile("cp.async.wait_group %0;" :: "n"(n) : "memory")

#define LDSM_X4(r0, r1, r2, r3, addr) \
    asm volatile("ldmatrix.sync.aligned.m8n8.x4.shared.b16 {%0,%1,%2,%3}, [%4];" \
                 : "=r"(r0), "=r"(r1), "=r"(r2), "=r"(r3) : "r"(addr))

#define LDSM_X4_T(r0, r1, r2, r3, addr) \
    asm volatile("ldmatrix.sync.aligned.m8n8.x4.trans.shared.b16 {%0,%1,%2,%3}, [%4];" \
                 : "=r"(r0), "=r"(r1), "=r"(r2), "=r"(r3) : "r"(addr))

#define MMAF16(d, a0, a1, a2, a3, b0, b1) \
    asm volatile("mma.sync.aligned.m16n8k16.row.col.f32.f16.f16.f32 " \
                 "{%0,%1,%2,%3}, {%4,%5,%6,%7}, {%8,%9}, {%0,%1,%2,%3};" \
                 : "+f"((d)[0]), "+f"((d)[1]), "+f"((d)[2]), "+f"((d)[3]) \
                 : "r"(a0), "r"(a1), "r"(a2), "r"(a3), "r"(b0), "r"(b1))

__device__ __forceinline__ uint32_t packh2(float a, float b) {
    __half2 h = __floats2half2_rn(a, b);
    return *reinterpret_cast<uint32_t*>(&h);
}

__device__ __forceinline__ void wait_cnt(const int* p, int target) {
    const volatile int* vp = (const volatile int*)p;
    while (*vp < target) __nanosleep(200);
}

// ---------------------------------------------------------------------------
// Counter reset prologue (separate launch: zeroing must precede increments)
// ---------------------------------------------------------------------------
__global__ void reset_cnt()
{
    const int t = threadIdx.x;
    if (t < 32) { g_mcnt[t] = 0; g_actx[t] = 0; g_xcnt[t] = 0; }
    if (t < 4)  g_misc[t] = 0;
}

// ---------------------------------------------------------------------------
// fp16 HMMA GEMM core: tile 128x128x64, 8 warps (4m x 2n), cp.async 2-stage.
// ---------------------------------------------------------------------------
static constexpr int HROW   = 144;
static constexpr int HTILE  = 128 * HROW;         // 18432 per operand tile
static constexpr int HSTAGE = 2 * HTILE;          // A + B = 36864
static constexpr int HGEMM_SMEM = 2 * HSTAGE;     // 73728

__device__ __forceinline__ void gemm_core(const __half* Ab, const __half* Bb,
                                          uint32_t sb,
                                          int tid, int wm, int wn, int lid,
                                          float acc[2][8][4])
{
    constexpr int K = 1024;
    auto load_stage = [&](int kc, int buf) {
        const uint32_t base = sb + buf * HSTAGE;
#pragma unroll
        for (int i = 0; i < 8; i++) {
            int c = tid + i * 256;              // 0..2047 16B chunks
            int op = c >> 10;                   // 0=A 1=B
            int rem = c & 1023;
            int r = rem >> 3, q = rem & 7;
            const __half* s = (op ? Bb : Ab) + (size_t)r * K + kc * 64 + q * 8;
            cp16(base + op * HTILE + r * HROW + q * 16, s);
        }
    };

    const int lr = lid & 15;
    const int lh = (lid >> 4) << 4;

    load_stage(0, 0);
    CP_COMMIT();

    constexpr int nk = K >> 6;                   // 16
    for (int kc = 0; kc < nk; kc++) {
        const int buf = kc & 1;
        if (kc + 1 < nk) { load_stage(kc + 1, buf ^ 1); CP_COMMIT(); CP_WAIT(1); }
        else             { CP_WAIT(0); }
        __syncthreads();

        const uint32_t base = sb + buf * HSTAGE;
        const uint32_t aB = base +         (wm * 32 + lr) * HROW + lh;
        const uint32_t bB = base + HTILE + (wn * 64 + lr) * HROW + lh;

#pragma unroll
        for (int ks = 0; ks < 4; ks++) {
            const uint32_t ko = ks * 32;
            uint32_t a[2][4];
#pragma unroll
            for (int mi = 0; mi < 2; mi++)
                LDSM_X4(a[mi][0], a[mi][1], a[mi][2], a[mi][3],
                        aB + mi * 16 * HROW + ko);
            uint32_t b[8][2];
#pragma unroll
            for (int np = 0; np < 4; np++) {
                uint32_t t0, t1, t2, t3;
                LDSM_X4(t0, t1, t2, t3, bB + np * 16 * HROW + ko);
                b[np * 2][0] = t0; b[np * 2][1] = t2;
                b[np * 2 + 1][0] = t1; b[np * 2 + 1][1] = t3;
            }
#pragma unroll
            for (int mi = 0; mi < 2; mi++)
#pragma unroll
                for (int nj = 0; nj < 8; nj++)
                    MMAF16(acc[mi][nj], a[mi][0], a[mi][1], a[mi][2], a[mi][3],
                           b[nj][0], b[nj][1]);
        }
        __syncthreads();
    }
}

// ---------------------------------------------------------------------------
// MEGA kernel — conversions + four dependent families, one launch:
//  bid [0,320):     convert (ungated): 0-127 x->fp16 (32 rows each, bumps
//                   g_xcnt/xall); 128-319 weight transpose strips (bump wq/wkv/wo)
//  bid [320,1088):  qkv GEMM  (gated on g_xcnt[mb]==4 && wq==96; bumps g_mcnt)
//  bid [1088,1600): attention (ascending tiles; stage-gated on g_mcnt;
//                   bumps g_actx; writes CtxH)
//  bid [1600,2112): k/v GEMM  (gated on xall==128 && wkv==64; filler)
//  bid [2112,2368): out GEMM  (gated on wo==32 && g_actx[mb]==16)
// All gates point to lower bids -> in-order dispatch = no deadlock.
// ---------------------------------------------------------------------------
static constexpr int ROWB = 144;
static constexpr int QREG = 128 * ROWB;           // 18432
static constexpr int KSTG = 2 * 64 * ROWB;        // 18432

__global__ __launch_bounds__(256, 2)
void mega(const float* __restrict__ x,
          const float* __restrict__ w_qkv, const float* __restrict__ w_k,
          const float* __restrict__ w_v,  const float* __restrict__ w_o,
          const float* __restrict__ b_qkv, const float* __restrict__ b_k,
          const float* __restrict__ b_v,  const float* __restrict__ b_o,
          const float* __restrict__ pk,   const float* __restrict__ pv,
          __half* __restrict__ Xh, __half* __restrict__ WH,
          __half* __restrict__ WoH,
          __half* __restrict__ QKVH, __half* __restrict__ ctxh,
          float* __restrict__ out, float* __restrict__ kcol,
          float* __restrict__ vcol)
{
    extern __shared__ char sm[];
    const uint32_t sb = smem_u32(sm);
    const int bid = blockIdx.x;
    const int tid = threadIdx.x;
    const int wid = tid >> 5, lid = tid & 31;
    const int wm  = wid >> 1, wn = wid & 1;

    if (bid < 128) {
        // ---------------- x -> fp16 (32 rows = 8192 float4) ----------------
        const float* xs = x + (size_t)bid * 32 * 1024;
        __half* xd = Xh + (size_t)bid * 32 * 1024;
#pragma unroll
        for (int j = 0; j < 32; j++) {
            int idx = j * 256 + tid;
            float4 v = reinterpret_cast<const float4*>(xs)[idx];
            reinterpret_cast<__half2*>(xd)[2 * idx + 0] = __floats2half2_rn(v.x, v.y);
            reinterpret_cast<__half2*>(xd)[2 * idx + 1] = __floats2half2_rn(v.z, v.w);
        }
        __threadfence();
        __syncthreads();
        if (tid == 0) {
            atomicAdd(&g_xcnt[bid >> 2], 1);
            atomicAdd(&g_misc[3], 1);
        }
        return;
    }

    if (bid < 320) {
        // -------- weight transpose strip: 32 n-cols x full K = 1024 --------
        int t = bid - 128;
        const float* W;
        __half* T;
        int N;
        int* cnt;
        if (t < 96)       { W = w_qkv; T = WH;               N = 3072; cnt = &g_misc[0]; }
        else if (t < 128) { W = w_k;   T = WH + 3072 * 1024; N = 1024; cnt = &g_misc[1]; t -= 96; }
        else if (t < 160) { W = w_v;   T = WH + 4096 * 1024; N = 1024; cnt = &g_misc[1]; t -= 128; }
        else              { W = w_o;   T = WoH;              N = 1024; cnt = &g_misc[2]; t -= 160; }
        const int n0 = t * 32;
        const int tx = tid & 31, ty = tid >> 5;    // (32, 8)
        float* tt = reinterpret_cast<float*>(sm);  // [32][33]

        for (int k0 = 0; k0 < 1024; k0 += 32) {
#pragma unroll
            for (int i = 0; i < 4; i++)
                tt[(ty + i * 8) * 33 + tx] =
                    W[(size_t)(k0 + ty + i * 8) * N + n0 + tx];
            __syncthreads();
#pragma unroll
            for (int i = 0; i < 4; i++)
                T[(size_t)(n0 + ty + i * 8) * 1024 + k0 + tx] =
                    __float2half_rn(tt[tx * 33 + ty + i * 8]);
            __syncthreads();
        }
        __threadfence();
        __syncthreads();
        if (tid == 0) atomicAdd(cnt, 1);
        return;
    }

    if (bid < 1088) {
        // ---------------- qkv projection GEMM (convert-gated) ----------------
        const int qbid = bid - 320;
        const int mIdx = qbid / 24;
        const int mb   = (mIdx & 3) * 8 + (mIdx >> 2);   // tile-0 of all b first
        const int m0   = mb * 128;
        const int n0   = (qbid % 24) * 128;

        wait_cnt(&g_xcnt[mb], 4);
        wait_cnt(&g_misc[0], 96);
        __threadfence();

        float acc[2][8][4];
#pragma unroll
        for (int i = 0; i < 2; i++)
#pragma unroll
            for (int j = 0; j < 8; j++)
#pragma unroll
                for (int v = 0; v < 4; v++) acc[i][j][v] = 0.f;

        gemm_core(Xh + (size_t)m0 * 1024, WH + (size_t)n0 * 1024,
                  sb, tid, wm, wn, lid, acc);

#pragma unroll
        for (int mi = 0; mi < 2; mi++) {
#pragma unroll
            for (int nj = 0; nj < 8; nj++) {
                const int col = n0 + wn * 64 + nj * 8 + (lid & 3) * 2;
                const float2 bv = *reinterpret_cast<const float2*>(b_qkv + col);
#pragma unroll
                for (int half_ = 0; half_ < 2; half_++) {
                    const int row = m0 + wm * 32 + mi * 16 + (lid >> 2) + half_ * 8;
                    *reinterpret_cast<uint32_t*>(&QKVH[(size_t)row * 3072 + col]) =
                        packh2(acc[mi][nj][half_ * 2 + 0] + bv.x,
                               acc[mi][nj][half_ * 2 + 1] + bv.y);
                }
            }
        }
        __threadfence();
        __syncthreads();
        if (tid == 0) atomicAdd(&g_mcnt[mb], 1);
        return;
    }

    if (bid >= 2112) {
        // ---------------- output projection GEMM (gated on ctx + wo) --------
        const int obid = bid - 2112;
        const int mb   = obid >> 3;
        const int m0   = mb * 128;
        const int n0   = (obid & 7) * 128;

        wait_cnt(&g_misc[2], 32);
        wait_cnt(&g_actx[mb], 16);
        __threadfence();

        float acc[2][8][4];
#pragma unroll
        for (int i = 0; i < 2; i++)
#pragma unroll
            for (int j = 0; j < 8; j++)
#pragma unroll
                for (int v = 0; v < 4; v++) acc[i][j][v] = 0.f;

        gemm_core(ctxh + (size_t)m0 * 1024, WoH + (size_t)n0 * 1024,
                  sb, tid, wm, wn, lid, acc);

#pragma unroll
        for (int mi = 0; mi < 2; mi++) {
#pragma unroll
            for (int nj = 0; nj < 8; nj++) {
                const int col = n0 + wn * 64 + nj * 8 + (lid & 3) * 2;
                const float2 bv = *reinterpret_cast<const float2*>(b_o + col);
#pragma unroll
                for (int half_ = 0; half_ < 2; half_++) {
                    const int row = m0 + wm * 32 + mi * 16 + (lid >> 2) + half_ * 8;
                    float2 o;
                    o.x = acc[mi][nj][half_ * 2 + 0] + bv.x;
                    o.y = acc[mi][nj][half_ * 2 + 1] + bv.y;
                    *reinterpret_cast<float2*>(&out[(size_t)row * Dc + col]) = o;
                }
            }
        }
        return;
    }

    if (bid >= 1600) {
        // ---------------- k/v projection GEMM (convert-gated filler) -------
        const int t  = bid - 1600;
        const int n0 = 3072 + (t & 15) * 128;
        const int m0 = (t >> 4) * 128;

        wait_cnt(&g_misc[3], 128);
        wait_cnt(&g_misc[1], 64);
        __threadfence();

        float acc[2][8][4];
#pragma unroll
        for (int i = 0; i < 2; i++)
#pragma unroll
            for (int j = 0; j < 8; j++)
#pragma unroll
                for (int v = 0; v < 4; v++) acc[i][j][v] = 0.f;

        gemm_core(Xh + (size_t)m0 * 1024, WH + (size_t)n0 * 1024,
                  sb, tid, wm, wn, lid, acc);

        const int seg = (n0 < 4096) ? 1 : 2;
        const float* bias = (seg == 1) ? b_k : b_v;
        const int segbase = (seg == 1) ? 3072 : 4096;
        float* dst = (seg == 1) ? kcol : vcol;

#pragma unroll
        for (int mi = 0; mi < 2; mi++) {
#pragma unroll
            for (int nj = 0; nj < 8; nj++) {
                const int col = n0 + wn * 64 + nj * 8 + (lid & 3) * 2;
                const int c = col - segbase;
                const float2 bv = *reinterpret_cast<const float2*>(bias + c);
#pragma unroll
                for (int half_ = 0; half_ < 2; half_++) {
                    const int row = m0 + wm * 32 + mi * 16 + (lid >> 2) + half_ * 8;
                    float2 o;
                    o.x = acc[mi][nj][half_ * 2 + 0] + bv.x;
                    o.y = acc[mi][nj][half_ * 2 + 1] + bv.y;
                    int b = row >> 10, s = row & 1023, h = c >> 6, d = c & 63;
                    *reinterpret_cast<float2*>(
                        &dst[(size_t)(((b * Hc + h) * Sc) + s) * HDc + d]) = o;
                }
            }
        }
        return;
    }

    // ---------------- attention path (ascending tiles, stage-gated) --------
    const int abid = bid - 1088;
    const int tile = abid >> 6;                  // ascending: matches producer order
    const int h    = abid & 15;
    const int b    = (abid >> 4) & 3;
    const int b8   = b * 8;

    const size_t qkv_row0 = (size_t)(b * Sc + tile * 128) * 3072;

    // Q tile gate + load
    wait_cnt(&g_mcnt[b8 + tile], 24);
#pragma unroll
    for (int i = 0; i < 4; i++) {
        int c = tid + i * 256;
        int rr = c >> 3, o = (c & 7) * 16;
        cp16(sb + rr * ROWB + o, QKVH + qkv_row0 + (size_t)rr * 3072 + h * 64 + o / 2);
    }
    CP_COMMIT();

    const int nkt = 2 * tile + 2;
    auto load_stage = [&](int kt, int buf) {
        const uint32_t st = sb + QREG + buf * KSTG;
        const size_t row0 = (size_t)(b * Sc + kt * 64) * 3072;
#pragma unroll
        for (int i = 0; i < 4; i++) {
            int c = tid + i * 256;
            int arr = c >> 9;
            int rem = c & 511;
            int rr = rem >> 3, o = (rem & 7) * 16;
            int colb = arr ? 2048 : 1024;
            cp16(st + arr * (64 * ROWB) + rr * ROWB + o,
                 QKVH + row0 + (size_t)rr * 3072 + colb + h * 64 + o / 2);
        }
    };
    wait_cnt(&g_mcnt[b8], 24);
    load_stage(0, 0);
    CP_COMMIT();

    CP_WAIT(1);
    __syncthreads();
    uint32_t qf[16];
    {
        const uint32_t qbase = sb + (wid * 16 + (lid & 15)) * ROWB + ((lid >> 4) << 4);
#pragma unroll
        for (int kc = 0; kc < 4; kc++)
            LDSM_X4(qf[kc * 4 + 0], qf[kc * 4 + 1], qf[kc * 4 + 2], qf[kc * 4 + 3],
                    qbase + kc * 32);
    }
    __syncthreads();

    float o_acc[8][4];
#pragma unroll
    for (int j = 0; j < 8; j++)
#pragma unroll
        for (int v = 0; v < 4; v++) o_acc[j][v] = 0.f;
    float m0 = -1e30f, m1 = -1e30f, sr0 = 0.f, sr1 = 0.f;

    const int rA = tile * 128 + wid * 16 + (lid >> 2);
    const int diag = 2 * tile;

    for (int kt = 0; kt < nkt; kt++) {
        const int buf = kt & 1;
        if (kt + 1 < nkt) {
            wait_cnt(&g_mcnt[b8 + ((kt + 1) >> 1)], 24);
            load_stage(kt + 1, buf ^ 1); CP_COMMIT(); CP_WAIT(1);
        } else {
            CP_WAIT(0);
        }
        __syncthreads();

        const uint32_t st = sb + QREG + buf * KSTG;
        const uint32_t Ks = st, Vs = st + 64 * ROWB;

        float s[8][4];
#pragma unroll
        for (int j = 0; j < 8; j++)
#pragma unroll
            for (int v = 0; v < 4; v++) s[j][v] = 0.f;

#pragma unroll
        for (int np = 0; np < 4; np++) {
            const uint32_t krow = (np * 16 + ((lid >> 4) & 1) * 8 + (lid & 7)) * ROWB
                                + ((lid >> 3) & 1) * 16;
#pragma unroll
            for (int kc = 0; kc < 4; kc++) {
                uint32_t k0, k1, k2, k3;
                LDSM_X4(k0, k1, k2, k3, Ks + krow + kc * 32);
                const uint32_t* qa = qf + kc * 4;
                MMAF16(s[2 * np],     qa[0], qa[1], qa[2], qa[3], k0, k1);
                MMAF16(s[2 * np + 1], qa[0], qa[1], qa[2], qa[3], k2, k3);
            }
        }

#pragma unroll
        for (int j = 0; j < 8; j++)
#pragma unroll
            for (int v = 0; v < 4; v++) s[j][v] *= 0.125f;
        if (kt >= diag) {
#pragma unroll
            for (int j = 0; j < 8; j++) {
                int c0 = kt * 64 + j * 8 + (lid & 3) * 2;
                if (c0     > rA)     s[j][0] = -1e30f;
                if (c0 + 1 > rA)     s[j][1] = -1e30f;
                if (c0     > rA + 8) s[j][2] = -1e30f;
                if (c0 + 1 > rA + 8) s[j][3] = -1e30f;
            }
        }

        float mx0 = -1e30f, mx1 = -1e30f;
#pragma unroll
        for (int j = 0; j < 8; j++) {
            mx0 = fmaxf(mx0, fmaxf(s[j][0], s[j][1]));
            mx1 = fmaxf(mx1, fmaxf(s[j][2], s[j][3]));
        }
        mx0 = fmaxf(mx0, __shfl_xor_sync(0xffffffffu, mx0, 1));
        mx0 = fmaxf(mx0, __shfl_xor_sync(0xffffffffu, mx0, 2));
        mx1 = fmaxf(mx1, __shfl_xor_sync(0xffffffffu, mx1, 1));
        mx1 = fmaxf(mx1, __shfl_xor_sync(0xffffffffu, mx1, 2));
        const float mn0 = fmaxf(m0, mx0), mn1 = fmaxf(m1, mx1);
        const float cr0 = __expf(m0 - mn0), cr1 = __expf(m1 - mn1);
        m0 = mn0; m1 = mn1;
        float ps0 = 0.f, ps1 = 0.f;
#pragma unroll
        for (int j = 0; j < 8; j++) {
            s[j][0] = __expf(s[j][0] - m0); ps0 += s[j][0];
            s[j][1] = __expf(s[j][1] - m0); ps0 += s[j][1];
            s[j][2] = __expf(s[j][2] - m1); ps1 += s[j][2];
            s[j][3] = __expf(s[j][3] - m1); ps1 += s[j][3];
        }
        ps0 += __shfl_xor_sync(0xffffffffu, ps0, 1);
        ps0 += __shfl_xor_sync(0xffffffffu, ps0, 2);
        ps1 += __shfl_xor_sync(0xffffffffu, ps1, 1);
        ps1 += __shfl_xor_sync(0xffffffffu, ps1, 2);
        sr0 = sr0 * cr0 + ps0;
        sr1 = sr1 * cr1 + ps1;
#pragma unroll
        for (int j = 0; j < 8; j++) {
            o_acc[j][0] *= cr0; o_acc[j][1] *= cr0;
            o_acc[j][2] *= cr1; o_acc[j][3] *= cr1;
        }

#pragma unroll
        for (int kc = 0; kc < 4; kc++) {
            uint32_t ph[4];
            ph[0] = packh2(s[2 * kc][0],     s[2 * kc][1]);
            ph[1] = packh2(s[2 * kc][2],     s[2 * kc][3]);
            ph[2] = packh2(s[2 * kc + 1][0], s[2 * kc + 1][1]);
            ph[3] = packh2(s[2 * kc + 1][2], s[2 * kc + 1][3]);
            const uint32_t vrow = (kc * 16 + ((lid >> 3) & 1) * 8 + (lid & 7)) * ROWB
                                + ((lid >> 4) & 1) * 16;
#pragma unroll
            for (int np = 0; np < 4; np++) {
                uint32_t v0, v1, v2, v3;
                LDSM_X4_T(v0, v1, v2, v3, Vs + vrow + np * 32);
                MMAF16(o_acc[2 * np],     ph[0], ph[1], ph[2], ph[3], v0, v1);
                MMAF16(o_acc[2 * np + 1], ph[0], ph[1], ph[2], ph[3], v2, v3);
            }
        }
        __syncthreads();
    }

    float* Os = reinterpret_cast<float*>(sm);           // [128][66]
    float* Ms = reinterpret_cast<float*>(sm + 33792);   // [128]
    float* Ss = Ms + 128;                               // [128]
    {
        const int ra = wid * 16 + (lid >> 2), rb = ra + 8;
#pragma unroll
        for (int j = 0; j < 8; j++) {
            const int col = j * 8 + (lid & 3) * 2;
            Os[ra * 66 + col]     = o_acc[j][0];
            Os[ra * 66 + col + 1] = o_acc[j][1];
            Os[rb * 66 + col]     = o_acc[j][2];
            Os[rb * 66 + col + 1] = o_acc[j][3];
        }
        if ((lid & 3) == 0) {
            Ms[ra] = m0; Ms[rb] = m1;
            Ss[ra] = sr0; Ss[rb] = sr1;
        }
    }
    __syncthreads();

    {
        const int row = tid >> 1, half_ = tid & 1;
        const int rg = tile * 128 + row;
        float q[32];
        {
            const size_t qo = (size_t)(b * Sc + rg) * 3072 + h * 64 + half_ * 32;
            const __half2* qh2 = reinterpret_cast<const __half2*>(QKVH + qo);
#pragma unroll
            for (int i = 0; i < 16; i++) {
                float2 f = __half22float2(qh2[i]);
                q[2 * i + 0] = f.x * 0.125f;
                q[2 * i + 1] = f.y * 0.125f;
            }
        }
        float m = Ms[row], sr = Ss[row];
        float acc[32];
#pragma unroll
        for (int i = 0; i < 32; i++) acc[i] = Os[row * 66 + half_ * 32 + i];

        const size_t pbase = ((size_t)((b * Hc + h) * Sc + rg)) * (Lc * HDc) + half_ * 32;
        const float* pkb = pk + pbase;
        const float* pvb = pv + pbase;
#pragma unroll 1
        for (int l = 0; l < Lc; l++) {
            float d0 = 0.f;
#pragma unroll
            for (int i = 0; i < 8; i++) {
                float4 kk = *reinterpret_cast<const float4*>(pkb + l * 64 + i * 4);
                d0 = fmaf(q[i * 4 + 0], kk.x, d0);
                d0 = fmaf(q[i * 4 + 1], kk.y, d0);
                d0 = fmaf(q[i * 4 + 2], kk.z, d0);
                d0 = fmaf(q[i * 4 + 3], kk.w, d0);
            }
            d0 += __shfl_xor_sync(0xffffffffu, d0, 1);
            float mn = fmaxf(m, d0);
            float cr = __expf(m - mn);
            float p = __expf(d0 - mn);
            m = mn;
            sr = sr * cr + p;
#pragma unroll
            for (int i = 0; i < 32; i++) acc[i] *= cr;
            const float4* vv4 = reinterpret_cast<const float4*>(pvb + l * 64);
#pragma unroll
            for (int i = 0; i < 8; i++) {
                float4 vv = vv4[i];
                acc[i * 4 + 0] = fmaf(p, vv.x, acc[i * 4 + 0]);
                acc[i * 4 + 1] = fmaf(p, vv.y, acc[i * 4 + 1]);
                acc[i * 4 + 2] = fmaf(p, vv.z, acc[i * 4 + 2]);
                acc[i * 4 + 3] = fmaf(p, vv.w, acc[i * 4 + 3]);
            }
        }
        const float inv = 1.f / sr;
        __half2* cp = reinterpret_cast<__half2*>(
            ctxh + (size_t)(b * Sc + rg) * Dc + h * 64 + half_ * 32);
#pragma unroll
        for (int i = 0; i < 16; i++)
            cp[i] = __floats2half2_rn(acc[2 * i] * inv, acc[2 * i + 1] * inv);
    }

    __threadfence();
    __syncthreads();
    if (tid == 0) atomicAdd(&g_actx[b8 + tile], 1);
}

// ---------------------------------------------------------------------------
extern "C" void kernel_launch(void* const* d_in, const int* in_sizes, int n_in,
                              void* d_out, int out_size)
{
    const float* x     = (const float*)d_in[0];
    const float* pk    = (const float*)d_in[1];
    const float* pv    = (const float*)d_in[2];
    const float* w_qkv = (const float*)d_in[3];
    const float* b_qkv = (const float*)d_in[4];
    const float* w_k   = (const float*)d_in[5];
    const float* b_k   = (const float*)d_in[6];
    const float* w_v   = (const float*)d_in[7];
    const float* b_v   = (const float*)d_in[8];
    const float* w_o   = (const float*)d_in[9];
    const float* b_o   = (const float*)d_in[10];

    float* out  = (float*)d_out;
    float* kcol = out + (size_t)Bc * Sc * Dc;
    float* vcol = kcol + (size_t)Bc * Hc * Sc * HDc;

    static __half *Xh, *CtxH, *WH, *WoH, *QKVH;
    static bool inited = false;
    if (!inited) {
        inited = true;
        cudaGetSymbolAddress((void**)&Xh, g_Xh);
        cudaGetSymbolAddress((void**)&CtxH, g_CtxH);
        cudaGetSymbolAddress((void**)&WH, g_WH);
        cudaGetSymbolAddress((void**)&WoH, g_WoH);
        cudaGetSymbolAddress((void**)&QKVH, g_QKVH);
        cudaFuncSetAttribute(mega,
                             cudaFuncAttributeMaxDynamicSharedMemorySize, HGEMM_SMEM);
    }

    // --- counter reset (must precede any increment) ---
    reset_cnt<<<1, 64>>>();

    // --- everything: one dependency-pipelined launch ---
    mega<<<2368, 256, HGEMM_SMEM>>>(x, w_qkv, w_k, w_v, w_o,
                                    b_qkv, b_k, b_v, b_o, pk, pv,
                                    Xh, WH, WoH, QKVH, CtxH,
                                    out, kcol, vcol);
}

// round 17
// speedup vs baseline: 1.0327x; 1.0327x over previous
#include <cuda_runtime.h>
#include <cuda_fp16.h>
#include <cstdint>
#include <math.h>

// Problem constants
static constexpr int Bc  = 4;
static constexpr int Sc  = 1024;
static constexpr int Dc  = 1024;
static constexpr int Hc  = 16;
static constexpr int HDc = 64;
static constexpr int Lc  = 12;
static constexpr int BS  = Bc * Sc;       // 4096 rows

// ---------------------------------------------------------------------------
// Scratch (__device__ globals; no cudaMalloc allowed)
// ---------------------------------------------------------------------------
__device__ __half g_Xh[(size_t)BS * Dc];          // fp16 x operand
__device__ __half g_CtxH[(size_t)BS * Dc];        // fp16 ctx (attn output)
__device__ __half g_WH[(size_t)5 * Dc * Dc];      // [wqkv^T; wk^T; wv^T] fp16
__device__ __half g_WoH[(size_t)Dc * Dc];         // w_o^T fp16
__device__ __half g_QKVH[(size_t)BS * 3 * Dc];    // qkv fp16 (attn operands)
__device__ int    g_mcnt[32];                     // qkv m-block done (-> 24)
__device__ int    g_actx[32];                     // ctx m-block done (-> 16)

// ---------------------------------------------------------------------------
// PTX helpers (base-PTX only: cp.async / ldmatrix / mma.sync)
// ---------------------------------------------------------------------------
__device__ __forceinline__ uint32_t smem_u32(const void* p) {
    uint32_t a;
    asm("{ .reg .u64 t; cvta.to.shared.u64 t, %1; cvt.u32.u64 %0, t; }"
        : "=r"(a) : "l"(p));
    return a;
}

__device__ __forceinline__ void cp16(uint32_t saddr, const void* gaddr) {
    asm volatile("cp.async.cg.shared.global [%0], [%1], 16;"
                 :: "r"(saddr), "l"(gaddr));
}
#define CP_COMMIT() asm volatile("cp.async.commit_group;" ::: "memory")
#define CP_WAIT(n)  asm volatile("cp.async.wait_group %0;" :: "n"(n) : "memory")

#define LDSM_X4(r0, r1, r2, r3, addr) \
    asm volatile("ldmatrix.sync.aligned.m8n8.x4.shared.b16 {%0,%1,%2,%3}, [%4];" \
                 : "=r"(r0), "=r"(r1), "=r"(r2), "=r"(r3) : "r"(addr))

#define LDSM_X4_T(r0, r1, r2, r3, addr) \
    asm volatile("ldmatrix.sync.aligned.m8n8.x4.trans.shared.b16 {%0,%1,%2,%3}, [%4];" \
                 : "=r"(r0), "=r"(r1), "=r"(r2), "=r"(r3) : "r"(addr))

#define MMAF16(d, a0, a1, a2, a3, b0, b1) \
    asm volatile("mma.sync.aligned.m16n8k16.row.col.f32.f16.f16.f32 " \
                 "{%0,%1,%2,%3}, {%4,%5,%6,%7}, {%8,%9}, {%0,%1,%2,%3};" \
                 : "+f"((d)[0]), "+f"((d)[1]), "+f"((d)[2]), "+f"((d)[3]) \
                 : "r"(a0), "r"(a1), "r"(a2), "r"(a3), "r"(b0), "r"(b1))

__device__ __forceinline__ uint32_t packh2(float a, float b) {
    __half2 h = __floats2half2_rn(a, b);
    return *reinterpret_cast<uint32_t*>(&h);
}

__device__ __forceinline__ void wait_cnt(const int* p, int target) {
    const volatile int* vp = (const volatile int*)p;
    while (*vp < target) __nanosleep(200);
}

// ---------------------------------------------------------------------------
// Mega-convert: blocks [0,1024): x -> fp16; blocks [1024,..): weight transposes
// Block 0 also zeroes the dependency counters for this invocation.
// ---------------------------------------------------------------------------
__global__ __launch_bounds__(256)
void convert_all(const float* __restrict__ x,
                 const float* __restrict__ w_qkv, const float* __restrict__ w_k,
                 const float* __restrict__ w_v,  const float* __restrict__ w_o,
                 __half* __restrict__ Xh, __half* __restrict__ WH,
                 __half* __restrict__ WoH)
{
    const int tx = threadIdx.x, ty = threadIdx.y;      // (32, 8)
    const int tid = ty * 32 + tx;
    const int bid = blockIdx.x;

    if (bid == 0 && tid < 32) { g_mcnt[tid] = 0; g_actx[tid] = 0; }

    if (bid < 1024) {
        const int idx = bid * 256 + tid;
#pragma unroll
        for (int j = 0; j < 4; j++) {
            int i = idx + j * 262144;
            float4 v = reinterpret_cast<const float4*>(x)[i];
            __half2 h01 = __floats2half2_rn(v.x, v.y);
            __half2 h23 = __floats2half2_rn(v.z, v.w);
            reinterpret_cast<__half2*>(Xh)[2 * i + 0] = h01;
            reinterpret_cast<__half2*>(Xh)[2 * i + 1] = h23;
        }
        return;
    }

    int t = bid - 1024;
    const float* W;
    __half* T;
    int N, tilesx;
    if (t < 3072)      { W = w_qkv; T = WH;                N = 3072; tilesx = 96; }
    else if (t < 4096) { W = w_k;   T = WH + 3072 * 1024;  N = 1024; tilesx = 32; t -= 3072; }
    else if (t < 5120) { W = w_v;   T = WH + 4096 * 1024;  N = 1024; tilesx = 32; t -= 4096; }
    else               { W = w_o;   T = WoH;               N = 1024; tilesx = 32; t -= 5120; }
    const int n0 = (t % tilesx) * 32;
    const int k0 = (t / tilesx) * 32;
    const int K = 1024;

    __shared__ float tt[32][33];
#pragma unroll
    for (int i = 0; i < 4; i++)
        tt[ty + i * 8][tx] = W[(size_t)(k0 + ty + i * 8) * N + n0 + tx];
    __syncthreads();
#pragma unroll
    for (int i = 0; i < 4; i++) {
        int n = n0 + ty + i * 8;
        T[(size_t)n * K + k0 + tx] = __float2half_rn(tt[tx][ty + i * 8]);
    }
}

// ---------------------------------------------------------------------------
// fp16 HMMA GEMM core: tile 128x128x64, 8 warps (4m x 2n), cp.async 2-stage.
// ---------------------------------------------------------------------------
static constexpr int HROW   = 144;
static constexpr int HTILE  = 128 * HROW;         // 18432 per operand tile
static constexpr int HSTAGE = 2 * HTILE;          // A + B = 36864
static constexpr int HGEMM_SMEM = 2 * HSTAGE;     // 73728

__device__ __forceinline__ void gemm_core(const __half* Ab, const __half* Bb,
                                          uint32_t sb,
                                          int tid, int wm, int wn, int lid,
                                          float acc[2][8][4])
{
    constexpr int K = 1024;
    auto load_stage = [&](int kc, int buf) {
        const uint32_t base = sb + buf * HSTAGE;
#pragma unroll
        for (int i = 0; i < 8; i++) {
            int c = tid + i * 256;              // 0..2047 16B chunks
            int op = c >> 10;                   // 0=A 1=B
            int rem = c & 1023;
            int r = rem >> 3, q = rem & 7;
            const __half* s = (op ? Bb : Ab) + (size_t)r * K + kc * 64 + q * 8;
            cp16(base + op * HTILE + r * HROW + q * 16, s);
        }
    };

    const int lr = lid & 15;
    const int lh = (lid >> 4) << 4;

    load_stage(0, 0);
    CP_COMMIT();

    constexpr int nk = K >> 6;                   // 16
    for (int kc = 0; kc < nk; kc++) {
        const int buf = kc & 1;
        if (kc + 1 < nk) { load_stage(kc + 1, buf ^ 1); CP_COMMIT(); CP_WAIT(1); }
        else             { CP_WAIT(0); }
        __syncthreads();

        const uint32_t base = sb + buf * HSTAGE;
        const uint32_t aB = base +         (wm * 32 + lr) * HROW + lh;
        const uint32_t bB = base + HTILE + (wn * 64 + lr) * HROW + lh;

#pragma unroll
        for (int ks = 0; ks < 4; ks++) {
            const uint32_t ko = ks * 32;
            uint32_t a[2][4];
#pragma unroll
            for (int mi = 0; mi < 2; mi++)
                LDSM_X4(a[mi][0], a[mi][1], a[mi][2], a[mi][3],
                        aB + mi * 16 * HROW + ko);
            uint32_t b[8][2];
#pragma unroll
            for (int np = 0; np < 4; np++) {
                uint32_t t0, t1, t2, t3;
                LDSM_X4(t0, t1, t2, t3, bB + np * 16 * HROW + ko);
                b[np * 2][0] = t0; b[np * 2][1] = t2;
                b[np * 2 + 1][0] = t1; b[np * 2 + 1][1] = t3;
            }
#pragma unroll
            for (int mi = 0; mi < 2; mi++)
#pragma unroll
                for (int nj = 0; nj < 8; nj++)
                    MMAF16(acc[mi][nj], a[mi][0], a[mi][1], a[mi][2], a[mi][3],
                           b[nj][0], b[nj][1]);
        }
        __syncthreads();
    }
}

// ---------------------------------------------------------------------------
// MEGA kernel — all four dependent families in one launch (R11 schedule):
//  bid [0,768):     qkv GEMM    (producer of QKVH; bumps g_mcnt[m-block])
//  bid [768,1280):  attention   (ASCENDING tiles; stage-gated on g_mcnt;
//                                bumps g_actx; writes CtxH)
//  bid [1280,1792): k/v GEMM    (independent filler; writes kcol/vcol)
//  bid [1792,2048): out GEMM    (gated on g_actx; writes out)
// All dependencies point to lower bids -> in-order dispatch = no deadlock.
// ---------------------------------------------------------------------------
static constexpr int ROWB = 144;
static constexpr int QREG = 128 * ROWB;           // 18432
static constexpr int KSTG = 2 * 64 * ROWB;        // 18432

__global__ __launch_bounds__(256, 2)
void mega(const __half* __restrict__ Xh, const __half* __restrict__ WH,
          const __half* __restrict__ WoH,
          const float* __restrict__ b_qkv, const float* __restrict__ b_k,
          const float* __restrict__ b_v,  const float* __restrict__ b_o,
          const float* __restrict__ pk,   const float* __restrict__ pv,
          __half* __restrict__ QKVH, __half* __restrict__ ctxh,
          float* __restrict__ out, float* __restrict__ kcol,
          float* __restrict__ vcol)
{
    extern __shared__ char sm[];
    const uint32_t sb = smem_u32(sm);
    const int bid = blockIdx.x;
    const int tid = threadIdx.x;
    const int wid = tid >> 5, lid = tid & 31;
    const int wm  = wid >> 1, wn = wid & 1;

    if (bid < 768) {
        // ---------------- qkv projection GEMM ----------------
        const int mIdx = bid / 24;
        const int mb   = (mIdx & 3) * 8 + (mIdx >> 2);   // tile-0 of all b first
        const int m0   = mb * 128;
        const int n0   = (bid % 24) * 128;

        float acc[2][8][4];
#pragma unroll
        for (int i = 0; i < 2; i++)
#pragma unroll
            for (int j = 0; j < 8; j++)
#pragma unroll
                for (int v = 0; v < 4; v++) acc[i][j][v] = 0.f;

        gemm_core(Xh + (size_t)m0 * 1024, WH + (size_t)n0 * 1024,
                  sb, tid, wm, wn, lid, acc);

#pragma unroll
        for (int mi = 0; mi < 2; mi++) {
#pragma unroll
            for (int nj = 0; nj < 8; nj++) {
                const int col = n0 + wn * 64 + nj * 8 + (lid & 3) * 2;
                const float2 bv = *reinterpret_cast<const float2*>(b_qkv + col);
#pragma unroll
                for (int half_ = 0; half_ < 2; half_++) {
                    const int row = m0 + wm * 32 + mi * 16 + (lid >> 2) + half_ * 8;
                    *reinterpret_cast<uint32_t*>(&QKVH[(size_t)row * 3072 + col]) =
                        packh2(acc[mi][nj][half_ * 2 + 0] + bv.x,
                               acc[mi][nj][half_ * 2 + 1] + bv.y);
                }
            }
        }
        __threadfence();
        __syncthreads();
        if (tid == 0) atomicAdd(&g_mcnt[mb], 1);
        return;
    }

    if (bid >= 1792) {
        // ---------------- output projection GEMM (gated on ctx) ----------------
        const int obid = bid - 1792;
        const int mb   = obid >> 3;
        const int m0   = mb * 128;
        const int n0   = (obid & 7) * 128;

        wait_cnt(&g_actx[mb], 16);
        __threadfence();

        float acc[2][8][4];
#pragma unroll
        for (int i = 0; i < 2; i++)
#pragma unroll
            for (int j = 0; j < 8; j++)
#pragma unroll
                for (int v = 0; v < 4; v++) acc[i][j][v] = 0.f;

        gemm_core(ctxh + (size_t)m0 * 1024, WoH + (size_t)n0 * 1024,
                  sb, tid, wm, wn, lid, acc);

#pragma unroll
        for (int mi = 0; mi < 2; mi++) {
#pragma unroll
            for (int nj = 0; nj < 8; nj++) {
                const int col = n0 + wn * 64 + nj * 8 + (lid & 3) * 2;
                const float2 bv = *reinterpret_cast<const float2*>(b_o + col);
#pragma unroll
                for (int half_ = 0; half_ < 2; half_++) {
                    const int row = m0 + wm * 32 + mi * 16 + (lid >> 2) + half_ * 8;
                    float2 o;
                    o.x = acc[mi][nj][half_ * 2 + 0] + bv.x;
                    o.y = acc[mi][nj][half_ * 2 + 1] + bv.y;
                    *reinterpret_cast<float2*>(&out[(size_t)row * Dc + col]) = o;
                }
            }
        }
        return;
    }

    if (bid >= 1280) {
        // ---------------- k/v projection GEMM (independent filler) ----------
        const int t  = bid - 1280;
        const int n0 = 3072 + (t & 15) * 128;
        const int m0 = (t >> 4) * 128;

        float acc[2][8][4];
#pragma unroll
        for (int i = 0; i < 2; i++)
#pragma unroll
            for (int j = 0; j < 8; j++)
#pragma unroll
                for (int v = 0; v < 4; v++) acc[i][j][v] = 0.f;

        gemm_core(Xh + (size_t)m0 * 1024, WH + (size_t)n0 * 1024,
                  sb, tid, wm, wn, lid, acc);

        const int seg = (n0 < 4096) ? 1 : 2;
        const float* bias = (seg == 1) ? b_k : b_v;
        const int segbase = (seg == 1) ? 3072 : 4096;
        float* dst = (seg == 1) ? kcol : vcol;

#pragma unroll
        for (int mi = 0; mi < 2; mi++) {
#pragma unroll
            for (int nj = 0; nj < 8; nj++) {
                const int col = n0 + wn * 64 + nj * 8 + (lid & 3) * 2;
                const int c = col - segbase;
                const float2 bv = *reinterpret_cast<const float2*>(bias + c);
#pragma unroll
                for (int half_ = 0; half_ < 2; half_++) {
                    const int row = m0 + wm * 32 + mi * 16 + (lid >> 2) + half_ * 8;
                    float2 o;
                    o.x = acc[mi][nj][half_ * 2 + 0] + bv.x;
                    o.y = acc[mi][nj][half_ * 2 + 1] + bv.y;
                    int b = row >> 10, s = row & 1023, h = c >> 6, d = c & 63;
                    *reinterpret_cast<float2*>(
                        &dst[(size_t)(((b * Hc + h) * Sc) + s) * HDc + d]) = o;
                }
            }
        }
        return;
    }

    // ---------------- attention path (ascending tiles, stage-gated) ------------
    const int abid = bid - 768;
    const int tile = abid >> 6;                  // ascending: matches producer order
    const int h    = abid & 15;
    const int b    = (abid >> 4) & 3;
    const int b8   = b * 8;

    const size_t qkv_row0 = (size_t)(b * Sc + tile * 128) * 3072;

    // Q tile gate + load
    wait_cnt(&g_mcnt[b8 + tile], 24);
#pragma unroll
    for (int i = 0; i < 4; i++) {
        int c = tid + i * 256;
        int rr = c >> 3, o = (c & 7) * 16;
        cp16(sb + rr * ROWB + o, QKVH + qkv_row0 + (size_t)rr * 3072 + h * 64 + o / 2);
    }
    CP_COMMIT();

    const int nkt = 2 * tile + 2;
    auto load_stage = [&](int kt, int buf) {
        const uint32_t st = sb + QREG + buf * KSTG;
        const size_t row0 = (size_t)(b * Sc + kt * 64) * 3072;
#pragma unroll
        for (int i = 0; i < 4; i++) {
            int c = tid + i * 256;
            int arr = c >> 9;
            int rem = c & 511;
            int rr = rem >> 3, o = (rem & 7) * 16;
            int colb = arr ? 2048 : 1024;
            cp16(st + arr * (64 * ROWB) + rr * ROWB + o,
                 QKVH + row0 + (size_t)rr * 3072 + colb + h * 64 + o / 2);
        }
    };
    wait_cnt(&g_mcnt[b8], 24);
    load_stage(0, 0);
    CP_COMMIT();

    CP_WAIT(1);
    __syncthreads();
    uint32_t qf[16];
    {
        const uint32_t qbase = sb + (wid * 16 + (lid & 15)) * ROWB + ((lid >> 4) << 4);
#pragma unroll
        for (int kc = 0; kc < 4; kc++)
            LDSM_X4(qf[kc * 4 + 0], qf[kc * 4 + 1], qf[kc * 4 + 2], qf[kc * 4 + 3],
                    qbase + kc * 32);
    }
    __syncthreads();

    float o_acc[8][4];
#pragma unroll
    for (int j = 0; j < 8; j++)
#pragma unroll
        for (int v = 0; v < 4; v++) o_acc[j][v] = 0.f;
    float m0 = -1e30f, m1 = -1e30f, sr0 = 0.f, sr1 = 0.f;

    const int rA = tile * 128 + wid * 16 + (lid >> 2);
    const int diag = 2 * tile;

    for (int kt = 0; kt < nkt; kt++) {
        const int buf = kt & 1;
        if (kt + 1 < nkt) {
            wait_cnt(&g_mcnt[b8 + ((kt + 1) >> 1)], 24);
            load_stage(kt + 1, buf ^ 1); CP_COMMIT(); CP_WAIT(1);
        } else {
            CP_WAIT(0);
        }
        __syncthreads();

        const uint32_t st = sb + QREG + buf * KSTG;
        const uint32_t Ks = st, Vs = st + 64 * ROWB;

        float s[8][4];
#pragma unroll
        for (int j = 0; j < 8; j++)
#pragma unroll
            for (int v = 0; v < 4; v++) s[j][v] = 0.f;

#pragma unroll
        for (int np = 0; np < 4; np++) {
            const uint32_t krow = (np * 16 + ((lid >> 4) & 1) * 8 + (lid & 7)) * ROWB
                                + ((lid >> 3) & 1) * 16;
#pragma unroll
            for (int kc = 0; kc < 4; kc++) {
                uint32_t k0, k1, k2, k3;
                LDSM_X4(k0, k1, k2, k3, Ks + krow + kc * 32);
                const uint32_t* qa = qf + kc * 4;
                MMAF16(s[2 * np],     qa[0], qa[1], qa[2], qa[3], k0, k1);
                MMAF16(s[2 * np + 1], qa[0], qa[1], qa[2], qa[3], k2, k3);
            }
        }

#pragma unroll
        for (int j = 0; j < 8; j++)
#pragma unroll
            for (int v = 0; v < 4; v++) s[j][v] *= 0.125f;
        if (kt >= diag) {
#pragma unroll
            for (int j = 0; j < 8; j++) {
                int c0 = kt * 64 + j * 8 + (lid & 3) * 2;
                if (c0     > rA)     s[j][0] = -1e30f;
                if (c0 + 1 > rA)     s[j][1] = -1e30f;
                if (c0     > rA + 8) s[j][2] = -1e30f;
                if (c0 + 1 > rA + 8) s[j][3] = -1e30f;
            }
        }

        float mx0 = -1e30f, mx1 = -1e30f;
#pragma unroll
        for (int j = 0; j < 8; j++) {
            mx0 = fmaxf(mx0, fmaxf(s[j][0], s[j][1]));
            mx1 = fmaxf(mx1, fmaxf(s[j][2], s[j][3]));
        }
        mx0 = fmaxf(mx0, __shfl_xor_sync(0xffffffffu, mx0, 1));
        mx0 = fmaxf(mx0, __shfl_xor_sync(0xffffffffu, mx0, 2));
        mx1 = fmaxf(mx1, __shfl_xor_sync(0xffffffffu, mx1, 1));
        mx1 = fmaxf(mx1, __shfl_xor_sync(0xffffffffu, mx1, 2));
        const float mn0 = fmaxf(m0, mx0), mn1 = fmaxf(m1, mx1);
        const float cr0 = __expf(m0 - mn0), cr1 = __expf(m1 - mn1);
        m0 = mn0; m1 = mn1;
        float ps0 = 0.f, ps1 = 0.f;
#pragma unroll
        for (int j = 0; j < 8; j++) {
            s[j][0] = __expf(s[j][0] - m0); ps0 += s[j][0];
            s[j][1] = __expf(s[j][1] - m0); ps0 += s[j][1];
            s[j][2] = __expf(s[j][2] - m1); ps1 += s[j][2];
            s[j][3] = __expf(s[j][3] - m1); ps1 += s[j][3];
        }
        ps0 += __shfl_xor_sync(0xffffffffu, ps0, 1);
        ps0 += __shfl_xor_sync(0xffffffffu, ps0, 2);
        ps1 += __shfl_xor_sync(0xffffffffu, ps1, 1);
        ps1 += __shfl_xor_sync(0xffffffffu, ps1, 2);
        sr0 = sr0 * cr0 + ps0;
        sr1 = sr1 * cr1 + ps1;
#pragma unroll
        for (int j = 0; j < 8; j++) {
            o_acc[j][0] *= cr0; o_acc[j][1] *= cr0;
            o_acc[j][2] *= cr1; o_acc[j][3] *= cr1;
        }

#pragma unroll
        for (int kc = 0; kc < 4; kc++) {
            uint32_t ph[4];
            ph[0] = packh2(s[2 * kc][0],     s[2 * kc][1]);
            ph[1] = packh2(s[2 * kc][2],     s[2 * kc][3]);
            ph[2] = packh2(s[2 * kc + 1][0], s[2 * kc + 1][1]);
            ph[3] = packh2(s[2 * kc + 1][2], s[2 * kc + 1][3]);
            const uint32_t vrow = (kc * 16 + ((lid >> 3) & 1) * 8 + (lid & 7)) * ROWB
                                + ((lid >> 4) & 1) * 16;
#pragma unroll
            for (int np = 0; np < 4; np++) {
                uint32_t v0, v1, v2, v3;
                LDSM_X4_T(v0, v1, v2, v3, Vs + vrow + np * 32);
                MMAF16(o_acc[2 * np],     ph[0], ph[1], ph[2], ph[3], v0, v1);
                MMAF16(o_acc[2 * np + 1], ph[0], ph[1], ph[2], ph[3], v2, v3);
            }
        }
        __syncthreads();
    }

    float* Os = reinterpret_cast<float*>(sm);           // [128][66]
    float* Ms = reinterpret_cast<float*>(sm + 33792);   // [128]
    float* Ss = Ms + 128;                               // [128]
    {
        const int ra = wid * 16 + (lid >> 2), rb = ra + 8;
#pragma unroll
        for (int j = 0; j < 8; j++) {
            const int col = j * 8 + (lid & 3) * 2;
            Os[ra * 66 + col]     = o_acc[j][0];
            Os[ra * 66 + col + 1] = o_acc[j][1];
            Os[rb * 66 + col]     = o_acc[j][2];
            Os[rb * 66 + col + 1] = o_acc[j][3];
        }
        if ((lid & 3) == 0) {
            Ms[ra] = m0; Ms[rb] = m1;
            Ss[ra] = sr0; Ss[rb] = sr1;
        }
    }
    __syncthreads();

    {
        const int row = tid >> 1, half_ = tid & 1;
        const int rg = tile * 128 + row;
        float q[32];
        {
            const size_t qo = (size_t)(b * Sc + rg) * 3072 + h * 64 + half_ * 32;
            const __half2* qh2 = reinterpret_cast<const __half2*>(QKVH + qo);
#pragma unroll
            for (int i = 0; i < 16; i++) {
                float2 f = __half22float2(qh2[i]);
                q[2 * i + 0] = f.x * 0.125f;
                q[2 * i + 1] = f.y * 0.125f;
            }
        }
        float m = Ms[row], sr = Ss[row];
        float acc[32];
#pragma unroll
        for (int i = 0; i < 32; i++) acc[i] = Os[row * 66 + half_ * 32 + i];

        const size_t pbase = ((size_t)((b * Hc + h) * Sc + rg)) * (Lc * HDc) + half_ * 32;
        const float* pkb = pk + pbase;
        const float* pvb = pv + pbase;
#pragma unroll 1
        for (int l = 0; l < Lc; l++) {
            float d0 = 0.f;
#pragma unroll
            for (int i = 0; i < 8; i++) {
                float4 kk = *reinterpret_cast<const float4*>(pkb + l * 64 + i * 4);
                d0 = fmaf(q[i * 4 + 0], kk.x, d0);
                d0 = fmaf(q[i * 4 + 1], kk.y, d0);
                d0 = fmaf(q[i * 4 + 2], kk.z, d0);
                d0 = fmaf(q[i * 4 + 3], kk.w, d0);
            }
            d0 += __shfl_xor_sync(0xffffffffu, d0, 1);
            float mn = fmaxf(m, d0);
            float cr = __expf(m - mn);
            float p = __expf(d0 - mn);
            m = mn;
            sr = sr * cr + p;
#pragma unroll
            for (int i = 0; i < 32; i++) acc[i] *= cr;
            const float4* vv4 = reinterpret_cast<const float4*>(pvb + l * 64);
#pragma unroll
            for (int i = 0; i < 8; i++) {
                float4 vv = vv4[i];
                acc[i * 4 + 0] = fmaf(p, vv.x, acc[i * 4 + 0]);
                acc[i * 4 + 1] = fmaf(p, vv.y, acc[i * 4 + 1]);
                acc[i * 4 + 2] = fmaf(p, vv.z, acc[i * 4 + 2]);
                acc[i * 4 + 3] = fmaf(p, vv.w, acc[i * 4 + 3]);
            }
        }
        const float inv = 1.f / sr;
        __half2* cp = reinterpret_cast<__half2*>(
            ctxh + (size_t)(b * Sc + rg) * Dc + h * 64 + half_ * 32);
#pragma unroll
        for (int i = 0; i < 16; i++)
            cp[i] = __floats2half2_rn(acc[2 * i] * inv, acc[2 * i + 1] * inv);
    }

    __threadfence();
    __syncthreads();
    if (tid == 0) atomicAdd(&g_actx[b8 + tile], 1);
}

// ---------------------------------------------------------------------------
extern "C" void kernel_launch(void* const* d_in, const int* in_sizes, int n_in,
                              void* d_out, int out_size)
{
    const float* x     = (const float*)d_in[0];
    const float* pk    = (const float*)d_in[1];
    const float* pv    = (const float*)d_in[2];
    const float* w_qkv = (const float*)d_in[3];
    const float* b_qkv = (const float*)d_in[4];
    const float* w_k   = (const float*)d_in[5];
    const float* b_k   = (const float*)d_in[6];
    const float* w_v   = (const float*)d_in[7];
    const float* b_v   = (const float*)d_in[8];
    const float* w_o   = (const float*)d_in[9];
    const float* b_o   = (const float*)d_in[10];

    float* out  = (float*)d_out;
    float* kcol = out + (size_t)Bc * Sc * Dc;
    float* vcol = kcol + (size_t)Bc * Hc * Sc * HDc;

    static __half *Xh, *CtxH, *WH, *WoH, *QKVH;
    static bool inited = false;
    if (!inited) {
        inited = true;
        cudaGetSymbolAddress((void**)&Xh, g_Xh);
        cudaGetSymbolAddress((void**)&CtxH, g_CtxH);
        cudaGetSymbolAddress((void**)&WH, g_WH);
        cudaGetSymbolAddress((void**)&WoH, g_WoH);
        cudaGetSymbolAddress((void**)&QKVH, g_QKVH);
        cudaFuncSetAttribute(mega,
                             cudaFuncAttributeMaxDynamicSharedMemorySize, HGEMM_SMEM);
    }

    // --- conversions + counter reset ---
    convert_all<<<7168, dim3(32, 8)>>>(x, w_qkv, w_k, w_v, w_o, Xh, WH, WoH);

    // --- everything else: one dependency-pipelined launch (R11 schedule) ---
    mega<<<2048, 256, HGEMM_SMEM>>>(Xh, WH, WoH, b_qkv, b_k, b_v, b_o,
                                    pk, pv, QKVH, CtxH, out, kcol, vcol);
}